// round 6
// baseline (speedup 1.0000x reference)
#include <cuda_runtime.h>
#include <cstdint>

// BinLinear: out = input @ sign(tanh(weight));  sign(tanh(w)) = +1 iff w >= 0.
// Exact decomposition for ANY weight:
//   out[n,o] = rowsum(input)[n] - 2 * sum_{(i,o): w[i,o] < 0} input[n,i]
//
// SINGLE persistent kernel (512 co-resident blocks), three phases:
//   A) each block scans its 8KB weight slice -> private neg-pair list + count
//   B) grid barrier (atomic arrive/spin; all blocks resident => safe)
//   C) each block computes rowsum+broadcast for its 16 rows, applying any
//      corrections itself (no atomics races across blocks: rows are owned).
// For weight ~ U[0,1) the lists are empty and phase C is pure streaming.

#define N_ROWS 8192
#define N_IP   2048
#define N_OP   2048
#define NB     512
#define TPB    256
#define ROWS_PER_BLK      16          // 8192 / 512
#define W4_PER_BLK        2048        // (2048*2048/4) / 512
#define PAIRS_PER_BLK     8192        // worst case: whole slice negative

// Persistent device state. g_cnt is fully rewritten each launch before use.
// Barrier counters self-reset each launch (release-counter pattern), so the
// kernel is graph-replay deterministic.
__device__ unsigned g_pairs[(size_t)NB * PAIRS_PER_BLK];
__device__ int      g_cnt[NB];
__device__ int      g_arrive;    // zero-init at load; returns to 0 each launch
__device__ int      g_release;   // zero-init at load; returns to 0 each launch

__global__ void __launch_bounds__(TPB, 4)
fused_binlinear_kernel(const float* __restrict__ x,
                       const float* __restrict__ w,
                       float* __restrict__ out) {
    const int b   = blockIdx.x;
    const int tid = threadIdx.x;
    const int lane = tid & 31;
    const int wid  = tid >> 5;

    __shared__ int   s_blkcnt;
    __shared__ int   s_tot;
    __shared__ float s_warp[8];

    if (tid == 0) s_blkcnt = 0;
    __syncthreads();

    // ---------------- Phase A: scan this block's weight slice ----------------
    const float4* w4 = reinterpret_cast<const float4*>(w) + (size_t)b * W4_PER_BLK;
    #pragma unroll
    for (int g = 0; g < 2; ++g) {
        float4 v[4];
        #pragma unroll
        for (int k = 0; k < 4; ++k) v[k] = __ldcs(&w4[tid + (g * 4 + k) * TPB]);

        float mn = v[0].x;
        #pragma unroll
        for (int k = 0; k < 4; ++k) {
            mn = fminf(mn, fminf(fminf(v[k].x, v[k].y), fminf(v[k].z, v[k].w)));
        }
        if (mn < 0.f) {                      // rare path: record negatives
            #pragma unroll
            for (int k = 0; k < 4; ++k) {
                const unsigned f4idx = (unsigned)(b * W4_PER_BLK + tid + (g * 4 + k) * TPB);
                const float e[4] = {v[k].x, v[k].y, v[k].z, v[k].w};
                #pragma unroll
                for (int j = 0; j < 4; ++j) {
                    if (e[j] < 0.f) {
                        const int slot = atomicAdd(&s_blkcnt, 1);
                        g_pairs[(size_t)b * PAIRS_PER_BLK + slot] = f4idx * 4u + (unsigned)j;
                    }
                }
            }
        }
    }
    __syncthreads();

    // ---------------- Phase B: grid barrier (all 512 blocks resident) --------
    if (tid == 0) {
        g_cnt[b] = s_blkcnt;
        __threadfence();                       // publish list + count
        atomicAdd(&g_arrive, 1);
        while (atomicAdd(&g_arrive, 0) < NB) {}  // L2-resident spin
        __threadfence();
        const int r = atomicAdd(&g_release, 1);
        if (r == NB - 1) {                     // last through: reset for replay
            g_arrive  = 0;
            g_release = 0;
            __threadfence();
        }
    }
    __syncthreads();

    // Total negatives across all blocks (512 counts, 2 per thread).
    {
        int c = g_cnt[tid] + g_cnt[tid + TPB];
        #pragma unroll
        for (int o = 16; o > 0; o >>= 1) c += __shfl_xor_sync(0xffffffffu, c, o);
        if (lane == 0) s_warp[wid] = (float)c;
        __syncthreads();
        if (tid == 0) {
            int t = 0;
            #pragma unroll
            for (int k = 0; k < 8; ++k) t += (int)s_warp[k];
            s_tot = t;
        }
        __syncthreads();
    }
    const bool have_neg = (s_tot != 0);

    // ---------------- Phase C: rowsum + broadcast for 16 owned rows ----------
    #pragma unroll 1
    for (int r = 0; r < ROWS_PER_BLK; ++r) {
        const int row = b * ROWS_PER_BLK + r;
        const float4* xr = reinterpret_cast<const float4*>(x + (size_t)row * N_IP);

        const float4 a0 = __ldcs(&xr[tid]);
        const float4 a1 = __ldcs(&xr[tid + TPB]);
        float s = ((a0.x + a0.y) + (a0.z + a0.w)) +
                  ((a1.x + a1.y) + (a1.z + a1.w));

        #pragma unroll
        for (int o = 16; o > 0; o >>= 1) s += __shfl_xor_sync(0xffffffffu, s, o);
        if (lane == 0) s_warp[wid] = s;
        __syncthreads();
        if (wid == 0) {
            float t = (lane < 8) ? s_warp[lane] : 0.f;
            #pragma unroll
            for (int o = 4; o > 0; o >>= 1) t += __shfl_xor_sync(0xffffffffu, t, o);
            if (lane == 0) s_warp[0] = t;
        }
        __syncthreads();
        const float total = s_warp[0];

        const float4 o4 = make_float4(total, total, total, total);
        float4* orow = reinterpret_cast<float4*>(out + (size_t)row * N_OP);
        __stcs(&orow[tid], o4);
        __stcs(&orow[tid + TPB], o4);

        if (have_neg) {                        // exact corrections, row-owned
            __syncthreads();                   // base stores before RMW
            for (int b2 = 0; b2 < NB; ++b2) {
                const int cnt = g_cnt[b2];
                for (int p = tid; p < cnt; p += TPB) {
                    const unsigned pos = g_pairs[(size_t)b2 * PAIRS_PER_BLK + p];
                    const int i = (int)(pos >> 11);        // pos / 2048
                    const int o = (int)(pos & 2047u);      // pos % 2048
                    atomicAdd(&out[(size_t)row * N_OP + o],
                              -2.0f * x[(size_t)row * N_IP + i]);
                }
            }
        }
        __syncthreads();                       // smem reuse next row
    }
}

extern "C" void kernel_launch(void* const* d_in, const int* in_sizes, int n_in,
                              void* d_out, int out_size) {
    const float* x = (const float*)d_in[0];   // input  [8192, 2048] f32
    const float* w = (const float*)d_in[1];   // weight [2048, 2048] f32
    float* out = (float*)d_out;               // out    [8192, 2048] f32

    fused_binlinear_kernel<<<NB, TPB>>>(x, w, out);
}